// round 1
// baseline (speedup 1.0000x reference)
#include <cuda_runtime.h>

#define CH   6
#define ICH  3
#define HWSZ (512 * 512)
#define HW4  (HWSZ / 4)
#define NB   32
#define EPS  1e-5f
#define LOG2E 1.4426950408889634f

__global__ __launch_bounds__(256) void aff_softmax_kernel(
    const float* __restrict__ x,
    const float* __restrict__ w1, const float* __restrict__ b1,
    const float* __restrict__ g1, const float* __restrict__ be1,
    const float* __restrict__ m1, const float* __restrict__ v1,
    const float* __restrict__ w2, const float* __restrict__ b2,
    const float* __restrict__ g2, const float* __restrict__ be2,
    const float* __restrict__ m2, const float* __restrict__ v2,
    float* __restrict__ out)
{
    // ---- per-block fold of BN into conv weights (tiny, once per block) ----
    __shared__ float sW1[ICH][CH], sB1[ICH], sW2[CH][ICH], sB2[CH];
    {
        int t = threadIdx.x;
        if (t < ICH) {
            float inv = g1[t] * rsqrtf(v1[t] + EPS);
            sB1[t] = (b1[t] - m1[t]) * inv + be1[t];
            #pragma unroll
            for (int c = 0; c < CH; c++) sW1[t][c] = w1[t * CH + c] * inv;
        } else if (t >= 32 && t < 32 + CH) {
            int k = t - 32;
            float inv = g2[k] * rsqrtf(v2[k] + EPS);
            // fold log2(e) so softmax can use raw ex2.approx
            sB2[k] = ((b2[k] - m2[k]) * inv + be2[k]) * LOG2E;
            float invl = inv * LOG2E;
            #pragma unroll
            for (int o = 0; o < ICH; o++) sW2[k][o] = w2[k * ICH + o] * invl;
        }
    }
    __syncthreads();

    // ---- hoist folded weights to registers (one LDS each) ----
    float rW1[ICH][CH], rB1[ICH], rW2[CH][ICH], rB2[CH];
    #pragma unroll
    for (int o = 0; o < ICH; o++) {
        rB1[o] = sB1[o];
        #pragma unroll
        for (int c = 0; c < CH; c++) rW1[o][c] = sW1[o][c];
    }
    #pragma unroll
    for (int k = 0; k < CH; k++) {
        rB2[k] = sB2[k];
        #pragma unroll
        for (int o = 0; o < ICH; o++) rW2[k][o] = sW2[k][o];
    }

    unsigned int gi = blockIdx.x * blockDim.x + threadIdx.x;   // float4 index
    const unsigned int N4 = (unsigned int)NB * HW4;
    if (gi >= N4) return;

    unsigned int b  = gi >> 16;           // gi / HW4  (HW4 = 65536)
    unsigned int p4 = gi & (HW4 - 1);

    const float4* xp = reinterpret_cast<const float4*>(x)
                       + (size_t)b * (CH * HW4) + p4;

    // ---- front-batched channel loads: 6 independent LDG.128 ----
    float4 xv[CH];
    #pragma unroll
    for (int c = 0; c < CH; c++) xv[c] = xp[(size_t)c * HW4];

    float xa[CH][4];
    #pragma unroll
    for (int c = 0; c < CH; c++) {
        xa[c][0] = xv[c].x; xa[c][1] = xv[c].y;
        xa[c][2] = xv[c].z; xa[c][3] = xv[c].w;
    }

    float res[4];
    #pragma unroll
    for (int j = 0; j < 4; j++) {
        // layer 1: 6 -> 3, folded BN, ReLU
        float h1[ICH];
        #pragma unroll
        for (int o = 0; o < ICH; o++) {
            float a = rB1[o];
            #pragma unroll
            for (int c = 0; c < CH; c++) a = fmaf(rW1[o][c], xa[c][j], a);
            h1[o] = fmaxf(a, 0.0f);
        }
        // layer 2: 3 -> 6, folded BN * log2(e); softmax (no max-sub: BN keeps
        // |h2| far below fp32 exp overflow) fused with the weighted sum
        float s = 0.0f, acc = 0.0f;
        #pragma unroll
        for (int k = 0; k < CH; k++) {
            float h = rB2[k];
            #pragma unroll
            for (int o = 0; o < ICH; o++) h = fmaf(rW2[k][o], h1[o], h);
            float e;
            asm("ex2.approx.ftz.f32 %0, %1;" : "=f"(e) : "f"(h));
            s += e;
            acc = fmaf(xa[k][j], e, acc);
        }
        float r;
        asm("rcp.approx.ftz.f32 %0, %1;" : "=f"(r) : "f"(s));
        res[j] = acc * r;
    }

    reinterpret_cast<float4*>(out)[(size_t)b * HW4 + p4] =
        make_float4(res[0], res[1], res[2], res[3]);
}

extern "C" void kernel_launch(void* const* d_in, const int* in_sizes, int n_in,
                              void* d_out, int out_size)
{
    const float* x   = (const float*)d_in[0];
    const float* w1  = (const float*)d_in[1];
    const float* b1  = (const float*)d_in[2];
    const float* g1  = (const float*)d_in[3];
    const float* be1 = (const float*)d_in[4];
    const float* m1  = (const float*)d_in[5];
    const float* v1  = (const float*)d_in[6];
    const float* w2  = (const float*)d_in[7];
    const float* b2  = (const float*)d_in[8];
    const float* g2  = (const float*)d_in[9];
    const float* be2 = (const float*)d_in[10];
    const float* m2  = (const float*)d_in[11];
    const float* v2  = (const float*)d_in[12];
    float* out = (float*)d_out;

    const unsigned int N4 = (unsigned int)NB * HW4;   // 2,097,152 float4 groups
    dim3 block(256);
    dim3 grid((N4 + block.x - 1) / block.x);          // 8192 blocks
    aff_softmax_kernel<<<grid, block>>>(x, w1, b1, g1, be1, m1, v1,
                                        w2, b2, g2, be2, m2, v2, out);
}

// round 3
// speedup vs baseline: 1.0128x; 1.0128x over previous
#include <cuda_runtime.h>

#define CH   6
#define ICH  3
#define HWSZ (512 * 512)
#define HW4  (HWSZ / 4)
#define NB   32
#define EPS  1e-5f
#define LOG2E 1.4426950408889634f

// Each thread processes 8 pixels: the same float4 position in batch b and b+16.
// 12 front-batched LDG.128 per thread -> 6KB in flight per warp, hiding DRAM
// latency at low occupancy while the 45 weight registers are amortized 2x.

__global__ __launch_bounds__(256, 2) void aff_softmax_kernel(
    const float* __restrict__ x,
    const float* __restrict__ w1, const float* __restrict__ b1,
    const float* __restrict__ g1, const float* __restrict__ be1,
    const float* __restrict__ m1, const float* __restrict__ v1,
    const float* __restrict__ w2, const float* __restrict__ b2,
    const float* __restrict__ g2, const float* __restrict__ be2,
    const float* __restrict__ m2, const float* __restrict__ v2,
    float* __restrict__ out)
{
    // ---- per-block fold of BN into conv weights (tiny, once per block) ----
    __shared__ float sW1[ICH][CH], sB1[ICH], sW2[CH][ICH], sB2[CH];
    {
        int t = threadIdx.x;
        if (t < ICH) {
            float inv = g1[t] * rsqrtf(v1[t] + EPS);
            sB1[t] = (b1[t] - m1[t]) * inv + be1[t];
            #pragma unroll
            for (int c = 0; c < CH; c++) sW1[t][c] = w1[t * CH + c] * inv;
        } else if (t >= 32 && t < 32 + CH) {
            int k = t - 32;
            float inv = g2[k] * rsqrtf(v2[k] + EPS);
            sB2[k] = ((b2[k] - m2[k]) * inv + be2[k]) * LOG2E;  // fold log2(e)
            float invl = inv * LOG2E;
            #pragma unroll
            for (int o = 0; o < ICH; o++) sW2[k][o] = w2[k * ICH + o] * invl;
        }
    }
    __syncthreads();

    // ---- hoist folded weights to registers ----
    float rW1[ICH][CH], rB1[ICH], rW2[CH][ICH], rB2[CH];
    #pragma unroll
    for (int o = 0; o < ICH; o++) {
        rB1[o] = sB1[o];
        #pragma unroll
        for (int c = 0; c < CH; c++) rW1[o][c] = sW1[o][c];
    }
    #pragma unroll
    for (int k = 0; k < CH; k++) {
        rB2[k] = sB2[k];
        #pragma unroll
        for (int o = 0; o < ICH; o++) rW2[k][o] = sW2[k][o];
    }

    // gi in [0, 2^20): selects (b, p4) with b in [0,16); pair batch is b+16.
    unsigned int gi = blockIdx.x * blockDim.x + threadIdx.x;
    unsigned int b  = gi >> 16;            // 0..15
    unsigned int p4 = gi & (HW4 - 1);

    const size_t halfStride = (size_t)(NB / 2) * CH * HW4;   // b -> b+16 delta
    const float4* xp0 = reinterpret_cast<const float4*>(x)
                        + (size_t)b * (CH * HW4) + p4;
    const float4* xp1 = xp0 + halfStride;

    // ---- 12 front-batched independent LDG.128 ----
    float4 xv[2][CH];
    #pragma unroll
    for (int c = 0; c < CH; c++) xv[0][c] = xp0[(size_t)c * HW4];
    #pragma unroll
    for (int c = 0; c < CH; c++) xv[1][c] = xp1[(size_t)c * HW4];

    float4* op0 = reinterpret_cast<float4*>(out) + (size_t)b * HW4 + p4;
    float4* op1 = op0 + (size_t)(NB / 2) * HW4;

    #pragma unroll
    for (int h = 0; h < 2; h++) {
        float xa[CH][4];
        #pragma unroll
        for (int c = 0; c < CH; c++) {
            xa[c][0] = xv[h][c].x; xa[c][1] = xv[h][c].y;
            xa[c][2] = xv[h][c].z; xa[c][3] = xv[h][c].w;
        }

        float res[4];
        #pragma unroll
        for (int j = 0; j < 4; j++) {
            // layer 1: 6 -> 3, folded BN, ReLU
            float h1[ICH];
            #pragma unroll
            for (int o = 0; o < ICH; o++) {
                float a = rB1[o];
                #pragma unroll
                for (int c = 0; c < CH; c++) a = fmaf(rW1[o][c], xa[c][j], a);
                h1[o] = fmaxf(a, 0.0f);
            }
            // layer 2 (folded BN*log2e) + softmax fused with weighted sum.
            // No max-subtraction: BN keeps |h2| orders below fp32 exp range.
            float s = 0.0f, acc = 0.0f;
            #pragma unroll
            for (int k = 0; k < CH; k++) {
                float hh = rB2[k];
                #pragma unroll
                for (int o = 0; o < ICH; o++) hh = fmaf(rW2[k][o], h1[o], hh);
                float e;
                asm("ex2.approx.ftz.f32 %0, %1;" : "=f"(e) : "f"(hh));
                s += e;
                acc = fmaf(xa[k][j], e, acc);
            }
            float r;
            asm("rcp.approx.ftz.f32 %0, %1;" : "=f"(r) : "f"(s));
            res[j] = acc * r;
        }

        float4 o4 = make_float4(res[0], res[1], res[2], res[3]);
        if (h == 0) *op0 = o4; else *op1 = o4;
    }
}

extern "C" void kernel_launch(void* const* d_in, const int* in_sizes, int n_in,
                              void* d_out, int out_size)
{
    const float* x   = (const float*)d_in[0];
    const float* w1  = (const float*)d_in[1];
    const float* b1  = (const float*)d_in[2];
    const float* g1  = (const float*)d_in[3];
    const float* be1 = (const float*)d_in[4];
    const float* m1  = (const float*)d_in[5];
    const float* v1  = (const float*)d_in[6];
    const float* w2  = (const float*)d_in[7];
    const float* b2  = (const float*)d_in[8];
    const float* g2  = (const float*)d_in[9];
    const float* be2 = (const float*)d_in[10];
    const float* m2  = (const float*)d_in[11];
    const float* v2  = (const float*)d_in[12];
    float* out = (float*)d_out;

    // 2^20 threads, each handling 2 float4 groups (8 pixels)
    const unsigned int NT = (unsigned int)(NB / 2) * HW4;  // 1,048,576
    dim3 block(256);
    dim3 grid(NT / block.x);                               // 4096 blocks
    aff_softmax_kernel<<<grid, block>>>(x, w1, b1, g1, be1, m1, v1,
                                        w2, b2, g2, be2, m2, v2, out);
}

// round 8
// speedup vs baseline: 1.0588x; 1.0454x over previous
#include <cuda_runtime.h>

#define CH   6
#define ICH  3
#define HWSZ (512 * 512)
#define HW4  (HWSZ / 4)
#define NB   32
#define EPS  1e-5f
#define LOG2E 1.4426950408889634f
#define ITER 4

// Software-pipelined: each thread handles 4 float4 tiles (same p4, batches
// b0, b0+8, b0+16, b0+24 with b0 in [0,8)). Loads for tile i+1 are issued
// BEFORE computing tile i, so ~3KB/warp stays continuously in flight.
// Softmax shifted by channel-0 logit: e0 == 1, 5 ex2/pixel.

__global__ __launch_bounds__(256, 2) void aff_softmax_kernel(
    const float* __restrict__ x,
    const float* __restrict__ w1, const float* __restrict__ b1,
    const float* __restrict__ g1, const float* __restrict__ be1,
    const float* __restrict__ m1, const float* __restrict__ v1,
    const float* __restrict__ w2, const float* __restrict__ b2,
    const float* __restrict__ g2, const float* __restrict__ be2,
    const float* __restrict__ m2, const float* __restrict__ v2,
    float* __restrict__ out)
{
    // ---- per-block fold of BN into conv weights ----
    __shared__ float sW1[ICH][CH], sB1[ICH], sW2[CH][ICH], sB2[CH];
    {
        int t = threadIdx.x;
        if (t < ICH) {
            float inv = g1[t] * rsqrtf(v1[t] + EPS);
            sB1[t] = (b1[t] - m1[t]) * inv + be1[t];
            #pragma unroll
            for (int c = 0; c < CH; c++) sW1[t][c] = w1[t * CH + c] * inv;
        } else if (t >= 32 && t < 32 + CH) {
            int k = t - 32;
            float inv = g2[k] * rsqrtf(v2[k] + EPS);
            sB2[k] = ((b2[k] - m2[k]) * inv + be2[k]) * LOG2E;  // fold log2(e)
            float invl = inv * LOG2E;
            #pragma unroll
            for (int o = 0; o < ICH; o++) sW2[k][o] = w2[k * ICH + o] * invl;
        }
    }
    __syncthreads();

    // ---- hoist weights; layer2 as deltas vs channel 0 (softmax shift) ----
    float rW1[ICH][CH], rB1[ICH];
    float rW2d[CH - 1][ICH], rB2d[CH - 1];   // logit_k - logit_0, k=1..5
    #pragma unroll
    for (int o = 0; o < ICH; o++) {
        rB1[o] = sB1[o];
        #pragma unroll
        for (int c = 0; c < CH; c++) rW1[o][c] = sW1[o][c];
    }
    #pragma unroll
    for (int k = 1; k < CH; k++) {
        rB2d[k - 1] = sB2[k] - sB2[0];
        #pragma unroll
        for (int o = 0; o < ICH; o++) rW2d[k - 1][o] = sW2[k][o] - sW2[0][o];
    }

    // tid0 in [0, 2^19): p4 = low 16 bits, b0 = high 3 bits (0..7)
    unsigned int tid0 = blockIdx.x * blockDim.x + threadIdx.x;
    unsigned int p4 = tid0 & (HW4 - 1);
    unsigned int b0 = tid0 >> 16;

    const float4* xp = reinterpret_cast<const float4*>(x)
                       + (size_t)b0 * (CH * HW4) + p4;
    float4* op = reinterpret_cast<float4*>(out) + (size_t)b0 * HW4 + p4;
    const size_t xstep = (size_t)(NB / ITER) * CH * HW4;   // batch += 8
    const size_t ostep = (size_t)(NB / ITER) * HW4;

    float4 buf[2][CH];
    #pragma unroll
    for (int c = 0; c < CH; c++) buf[0][c] = xp[(size_t)c * HW4];

    #pragma unroll
    for (int it = 0; it < ITER; it++) {
        // prefetch next tile while current tile computes
        const float4* xpn = xp + xstep;
        if (it < ITER - 1) {
            #pragma unroll
            for (int c = 0; c < CH; c++)
                buf[(it + 1) & 1][c] = xpn[(size_t)c * HW4];
        }

        float xa[CH][4];
        #pragma unroll
        for (int c = 0; c < CH; c++) {
            float4 v = buf[it & 1][c];
            xa[c][0] = v.x; xa[c][1] = v.y; xa[c][2] = v.z; xa[c][3] = v.w;
        }

        float res[4];
        #pragma unroll
        for (int j = 0; j < 4; j++) {
            // layer 1: 6 -> 3, folded BN, ReLU
            float h1[ICH];
            #pragma unroll
            for (int o = 0; o < ICH; o++) {
                float a = rB1[o];
                #pragma unroll
                for (int c = 0; c < CH; c++) a = fmaf(rW1[o][c], xa[c][j], a);
                h1[o] = fmaxf(a, 0.0f);
            }
            // shifted softmax: e0 = 1, e_k = exp2(delta logit), k=1..5
            float s = 1.0f, acc = xa[0][j];
            #pragma unroll
            for (int k = 0; k < CH - 1; k++) {
                float hh = rB2d[k];
                #pragma unroll
                for (int o = 0; o < ICH; o++) hh = fmaf(rW2d[k][o], h1[o], hh);
                float e;
                asm("ex2.approx.ftz.f32 %0, %1;" : "=f"(e) : "f"(hh));
                s += e;
                acc = fmaf(xa[k + 1][j], e, acc);
            }
            float r;
            asm("rcp.approx.ftz.f32 %0, %1;" : "=f"(r) : "f"(s));
            res[j] = acc * r;
        }

        *op = make_float4(res[0], res[1], res[2], res[3]);
        xp = xpn;
        op += ostep;
    }
}

extern "C" void kernel_launch(void* const* d_in, const int* in_sizes, int n_in,
                              void* d_out, int out_size)
{
    const float* x   = (const float*)d_in[0];
    const float* w1  = (const float*)d_in[1];
    const float* b1  = (const float*)d_in[2];
    const float* g1  = (const float*)d_in[3];
    const float* be1 = (const float*)d_in[4];
    const float* m1  = (const float*)d_in[5];
    const float* v1  = (const float*)d_in[6];
    const float* w2  = (const float*)d_in[7];
    const float* b2  = (const float*)d_in[8];
    const float* g2  = (const float*)d_in[9];
    const float* be2 = (const float*)d_in[10];
    const float* m2  = (const float*)d_in[11];
    const float* v2  = (const float*)d_in[12];
    float* out = (float*)d_out;

    // (NB/ITER)=8 batch-groups x HW4 positions = 2^19 threads, 4 tiles each
    const unsigned int NT = (unsigned int)(NB / ITER) * HW4;  // 524,288
    dim3 block(256);
    dim3 grid(NT / block.x);                                  // 2048 blocks
    aff_softmax_kernel<<<grid, block>>>(x, w1, b1, g1, be1, m1, v1,
                                        w2, b2, g2, be2, m2, v2, out);
}

// round 9
// speedup vs baseline: 1.1541x; 1.0900x over previous
#include <cuda_runtime.h>

#define CH     6
#define ICH    3
#define HWSZ   (512 * 512)
#define HW4    (HWSZ / 4)
#define NB     32
#define EPS    1e-5f
#define LOG2E  1.4426950408889634f
#define ITER   8
#define STAGES 3
#define TPB    128

// cp.async 3-stage smem pipeline. Each thread handles 8 tiles (same p4,
// batches b0, b0+4, ..., b0+28). Tile loads go gmem->smem via LDGSTS,
// bypassing the register file: ~2 tiles/thread continuously in flight with
// no register double-buffer. Each thread consumes only its own smem slots,
// so cp.async.wait_group ordering suffices -- no __syncthreads in the loop.

__global__ __launch_bounds__(TPB, 5) void aff_softmax_kernel(
    const float* __restrict__ x,
    const float* __restrict__ w1, const float* __restrict__ b1,
    const float* __restrict__ g1, const float* __restrict__ be1,
    const float* __restrict__ m1, const float* __restrict__ v1,
    const float* __restrict__ w2, const float* __restrict__ b2,
    const float* __restrict__ g2, const float* __restrict__ be2,
    const float* __restrict__ m2, const float* __restrict__ v2,
    float* __restrict__ out)
{
    __shared__ float4 sbuf[STAGES][CH][TPB];
    __shared__ float sW1[ICH][CH], sB1[ICH], sW2[CH][ICH], sB2[CH];

    // ---- per-block fold of BN into conv weights ----
    {
        int t = threadIdx.x;
        if (t < ICH) {
            float inv = g1[t] * rsqrtf(v1[t] + EPS);
            sB1[t] = (b1[t] - m1[t]) * inv + be1[t];
            #pragma unroll
            for (int c = 0; c < CH; c++) sW1[t][c] = w1[t * CH + c] * inv;
        } else if (t >= 32 && t < 32 + CH) {
            int k = t - 32;
            float inv = g2[k] * rsqrtf(v2[k] + EPS);
            sB2[k] = ((b2[k] - m2[k]) * inv + be2[k]) * LOG2E;
            float invl = inv * LOG2E;
            #pragma unroll
            for (int o = 0; o < ICH; o++) sW2[k][o] = w2[k * ICH + o] * invl;
        }
    }
    __syncthreads();

    // ---- hoist weights; layer2 as deltas vs channel 0 (softmax shift) ----
    float rW1[ICH][CH], rB1[ICH];
    float rW2d[CH - 1][ICH], rB2d[CH - 1];
    #pragma unroll
    for (int o = 0; o < ICH; o++) {
        rB1[o] = sB1[o];
        #pragma unroll
        for (int c = 0; c < CH; c++) rW1[o][c] = sW1[o][c];
    }
    #pragma unroll
    for (int k = 1; k < CH; k++) {
        rB2d[k - 1] = sB2[k] - sB2[0];
        #pragma unroll
        for (int o = 0; o < ICH; o++) rW2d[k - 1][o] = sW2[k][o] - sW2[0][o];
    }

    // tid0 in [0, 2^18): p4 = low 16 bits, b0 = high 2 bits (0..3)
    unsigned int tid0 = blockIdx.x * TPB + threadIdx.x;
    unsigned int p4 = tid0 & (HW4 - 1);
    unsigned int b0 = tid0 >> 16;

    const float4* xp = reinterpret_cast<const float4*>(x)
                       + (size_t)b0 * (CH * HW4) + p4;
    float4* op = reinterpret_cast<float4*>(out) + (size_t)b0 * HW4 + p4;
    const size_t xstep = (size_t)(NB / ITER) * CH * HW4;   // batch += 4
    const size_t ostep = (size_t)(NB / ITER) * HW4;

    // this thread's smem slot base (stage 0, channel 0)
    unsigned int sslot =
        (unsigned int)__cvta_generic_to_shared(&sbuf[0][0][threadIdx.x]);
    const unsigned int cstride = TPB * (unsigned int)sizeof(float4);
    const unsigned int sstride = CH * cstride;

    // ---- prologue: prefetch STAGES-1 tiles ----
    #pragma unroll
    for (int s = 0; s < STAGES - 1; s++) {
        const float4* g = xp + (size_t)s * xstep;
        #pragma unroll
        for (int c = 0; c < CH; c++) {
            asm volatile("cp.async.cg.shared.global [%0], [%1], 16;"
                         :: "r"(sslot + s * sstride + c * cstride),
                            "l"(g + (size_t)c * HW4));
        }
        asm volatile("cp.async.commit_group;");
    }

    #pragma unroll
    for (int it = 0; it < ITER; it++) {
        // issue tile it+STAGES-1 (if any), then always commit one group
        if (it + STAGES - 1 < ITER) {
            const float4* g = xp + (size_t)(it + STAGES - 1) * xstep;
            int s = (it + STAGES - 1) % STAGES;
            #pragma unroll
            for (int c = 0; c < CH; c++) {
                asm volatile("cp.async.cg.shared.global [%0], [%1], 16;"
                             :: "r"(sslot + s * sstride + c * cstride),
                                "l"(g + (size_t)c * HW4));
            }
        }
        asm volatile("cp.async.commit_group;");
        // allow 2 newest groups pending -> tile `it` has landed
        asm volatile("cp.async.wait_group %0;" :: "n"(STAGES - 1));

        const int cur = it % STAGES;
        float xa[CH][4];
        #pragma unroll
        for (int c = 0; c < CH; c++) {
            float4 v = sbuf[cur][c][threadIdx.x];
            xa[c][0] = v.x; xa[c][1] = v.y; xa[c][2] = v.z; xa[c][3] = v.w;
        }

        float res[4];
        #pragma unroll
        for (int j = 0; j < 4; j++) {
            float h1[ICH];
            #pragma unroll
            for (int o = 0; o < ICH; o++) {
                float a = rB1[o];
                #pragma unroll
                for (int c = 0; c < CH; c++) a = fmaf(rW1[o][c], xa[c][j], a);
                h1[o] = fmaxf(a, 0.0f);
            }
            float s = 1.0f, acc = xa[0][j];
            #pragma unroll
            for (int k = 0; k < CH - 1; k++) {
                float hh = rB2d[k];
                #pragma unroll
                for (int o = 0; o < ICH; o++) hh = fmaf(rW2d[k][o], h1[o], hh);
                float e;
                asm("ex2.approx.ftz.f32 %0, %1;" : "=f"(e) : "f"(hh));
                s += e;
                acc = fmaf(xa[k + 1][j], e, acc);
            }
            float r;
            asm("rcp.approx.ftz.f32 %0, %1;" : "=f"(r) : "f"(s));
            res[j] = acc * r;
        }

        op[(size_t)it * ostep] = make_float4(res[0], res[1], res[2], res[3]);
    }
}

extern "C" void kernel_launch(void* const* d_in, const int* in_sizes, int n_in,
                              void* d_out, int out_size)
{
    const float* x   = (const float*)d_in[0];
    const float* w1  = (const float*)d_in[1];
    const float* b1  = (const float*)d_in[2];
    const float* g1  = (const float*)d_in[3];
    const float* be1 = (const float*)d_in[4];
    const float* m1  = (const float*)d_in[5];
    const float* v1  = (const float*)d_in[6];
    const float* w2  = (const float*)d_in[7];
    const float* b2  = (const float*)d_in[8];
    const float* g2  = (const float*)d_in[9];
    const float* be2 = (const float*)d_in[10];
    const float* m2  = (const float*)d_in[11];
    const float* v2  = (const float*)d_in[12];
    float* out = (float*)d_out;

    // (NB/ITER)=4 batch-groups x HW4 positions = 2^18 threads, 8 tiles each
    const unsigned int NT = (unsigned int)(NB / ITER) * HW4;  // 262,144
    dim3 block(TPB);
    dim3 grid(NT / block.x);                                  // 2048 blocks
    aff_softmax_kernel<<<grid, block>>>(x, w1, b1, g1, be1, m1, v1,
                                        w2, b2, g2, be2, m2, v2, out);
}